// round 16
// baseline (speedup 1.0000x reference)
#include <cuda_runtime.h>
#include <cuda_bf16.h>

#define HDIM 16
#define UDIM 7
#define HID  64
#define XDIM 23
#define CHUNK 512
#define NTHREADS 96

typedef unsigned long long u64;

__device__ __forceinline__ unsigned smem_u32(const void* p) {
    return (unsigned)__cvta_generic_to_shared(p);
}
__device__ __forceinline__ void cp16(unsigned dst, const void* src) {
    asm volatile("cp.async.cg.shared.global [%0], [%1], 16;" :: "r"(dst), "l"(src));
}
__device__ __forceinline__ void cp4(unsigned dst, const void* src) {
    asm volatile("cp.async.ca.shared.global [%0], [%1], 4;" :: "r"(dst), "l"(src));
}
__device__ __forceinline__ void cp_commit() {
    asm volatile("cp.async.commit_group;" ::: "memory");
}
__device__ __forceinline__ void cp_wait1() {
    asm volatile("cp.async.wait_group 1;" ::: "memory");
}

// packed f32x2 helpers
__device__ __forceinline__ u64 pack2(float lo, float hi) {
    u64 r; asm("mov.b64 %0, {%1, %2};" : "=l"(r) : "f"(lo), "f"(hi)); return r;
}
__device__ __forceinline__ float2 unpack2(u64 v) {
    float2 f; asm("mov.b64 {%0, %1}, %2;" : "=f"(f.x), "=f"(f.y) : "l"(v)); return f;
}
__device__ __forceinline__ u64 fma2(u64 a, u64 b, u64 c) {
    u64 r; asm("fma.rn.f32x2 %0, %1, %2, %3;" : "=l"(r) : "l"(a), "l"(b), "l"(c)); return r;
}
__device__ __forceinline__ u64 add2(u64 a, u64 b) {
    u64 r; asm("add.rn.f32x2 %0, %1, %2;" : "=l"(r) : "l"(a), "l"(b)); return r;
}

// accurate tanh: (e^{2x}-1)/(e^{2x}+1), clamped to avoid inf/inf
__device__ __forceinline__ float ftanh(float x) {
    x = fminf(fmaxf(x, -15.0f), 15.0f);
    float e = __expf(2.0f * x);
    return __fdividef(e - 1.0f, e + 1.0f);
}

// inline packed 64-dot over 16B-aligned smem; weights MUST be a register array
// (fully unrolled constant indexing keeps ptxas from spilling to local)
#define PACKDOT64(res, W, ZS, INIT)                                  \
    do {                                                             \
        const ulonglong2* _zp = (const ulonglong2*)(ZS);             \
        u64 _q0 = (INIT), _q1 = 0ull, _q2 = 0ull, _q3 = 0ull;        \
        _Pragma("unroll")                                            \
        for (int _j = 0; _j < 8; _j++) {                             \
            ulonglong2 _a = _zp[2 * _j];                             \
            ulonglong2 _b = _zp[2 * _j + 1];                         \
            _q0 = fma2((W)[4 * _j + 0], _a.x, _q0);                  \
            _q1 = fma2((W)[4 * _j + 1], _a.y, _q1);                  \
            _q2 = fma2((W)[4 * _j + 2], _b.x, _q2);                  \
            _q3 = fma2((W)[4 * _j + 3], _b.y, _q3);                  \
        }                                                            \
        _q0 = add2(_q0, _q1);                                        \
        _q2 = add2(_q2, _q3);                                        \
        _q0 = add2(_q0, _q2);                                        \
        float2 _f = unpack2(_q0);                                    \
        (res) = _f.x + _f.y;                                         \
    } while (0)

__global__ void __launch_bounds__(NTHREADS, 1) node_scan_kernel(
    const float* __restrict__ U,
    const float* __restrict__ W1, const float* __restrict__ b1,
    const float* __restrict__ W2, const float* __restrict__ b2,
    const float* __restrict__ W3, const float* __restrict__ b3,
    const float* __restrict__ wd, const float* __restrict__ bd,
    const float* __restrict__ wt, const float* __restrict__ bt,
    const float* __restrict__ wc, const float* __restrict__ bc,
    const float* __restrict__ h0,
    float* __restrict__ out, int T)
{
    __shared__ __align__(16) float ubuf[2][CHUNK * UDIM];
    __shared__ __align__(16) float z1s[HID];
    __shared__ __align__(16) float z2s[HID];
    __shared__ __align__(16) double sumz2[HID];

    const int tid = threadIdx.x;
    const float dt = 5.0f / 60.0f;
    const int n_chunks = (T + CHUNK - 1) / CHUNK;

    const bool is_s  = (tid < HID);                      // warps 0,1: neuron tid
    const bool is_ro = (tid >= HID) && (tid < HID + 3);  // warp 2 lanes 0..2

    auto copy_chunk = [&](int cc) {
        if (cc >= n_chunks) return;
        const int t0 = cc * CHUNK;
        const int nf = min(CHUNK, T - t0) * UDIM;
        const float* src = U + t0 * UDIM;
        float* dst = ubuf[cc & 1];
        const int nv = nf >> 2;
        for (int i = tid; i < nv; i += NTHREADS) cp16(smem_u32(dst + 4 * i), src + 4 * i);
        for (int i = (nv << 2) + tid; i < nf; i += NTHREADS) cp4(smem_u32(dst + i), src + i);
    };
    copy_chunk(0); cp_commit();
    copy_chunk(1); cp_commit();

    // ---------------- prologue (overlaps the in-flight cp.async) ----------------
    // Ap = packed P1 dot weights: dt*(W1h@W3) row  OR  dt*(W3^T@wsel)
    // Bp = packed W2 row (s-threads only)
    u64 Ap[32], Bp[32];
    float w1u[UDIM];
    float state = 0.0f, comp = 0.0f, du = 0.0f;
    u64 init1 = 0ull, init2 = 0ull;      // pack2(cinit,0) / pack2(b2,0)
    float* outp = nullptr;
    double accz2 = 0.0;

    if (is_s) {
        const int n = tid;
        float w1h[HDIM];
        #pragma unroll
        for (int i = 0; i < HDIM; i++) w1h[i] = W1[n * XDIM + i];
        #pragma unroll
        for (int i = 0; i < UDIM; i++) w1u[i] = W1[n * XDIM + HDIM + i];
        #pragma unroll
        for (int j = 0; j < 32; j++)
            Bp[j] = pack2(W2[n * HID + 2 * j], W2[n * HID + 2 * j + 1]);
        init2 = pack2(b2[n], 0.0f);
        // A = dt * (W1h @ W3) row n, packed
        #pragma unroll 4
        for (int j = 0; j < 32; j++) {
            float m0 = 0.0f, m1 = 0.0f;
            #pragma unroll
            for (int i = 0; i < HDIM; i++) {
                m0 = fmaf(w1h[i], W3[i * HID + 2 * j], m0);
                m1 = fmaf(w1h[i], W3[i * HID + 2 * j + 1], m1);
            }
            Ap[j] = pack2(dt * m0, dt * m1);
        }
        float cd = 0.0f;
        #pragma unroll
        for (int i = 0; i < HDIM; i++) cd = fmaf(w1h[i], b3[i], cd);
        const float cinit = dt * cd;
        init1 = pack2(cinit, 0.0f);
        // state seeded s0 - cinit so uniform "+cinit" is exact at t=0 (z2s = 0)
        float s0 = b1[n];
        #pragma unroll
        for (int i = 0; i < HDIM; i++) s0 = fmaf(w1h[i], h0[i], s0);
        state = s0 - cinit;
        z2s[n] = 0.0f;
    } else {
        #pragma unroll
        for (int j = 0; j < 32; j++) { Ap[j] = 0ull; Bp[j] = 0ull; }
        #pragma unroll
        for (int i = 0; i < UDIM; i++) w1u[i] = 0.0f;
        if (is_ro) {
            const int idx = tid - HID;
            const float* wsel = (idx == 0) ? wd : (idx == 1) ? wt : wc;
            const float bsel  = (idx == 0) ? bd[0] : (idx == 1) ? bt[0] : bc[0];
            float ws[HDIM];
            #pragma unroll
            for (int i = 0; i < HDIM; i++) ws[i] = wsel[i];
            #pragma unroll 4
            for (int j = 0; j < 32; j++) {
                float m0 = 0.0f, m1 = 0.0f;
                #pragma unroll
                for (int i = 0; i < HDIM; i++) {
                    m0 = fmaf(ws[i], W3[i * HID + 2 * j], m0);
                    m1 = fmaf(ws[i], W3[i * HID + 2 * j + 1], m1);
                }
                Ap[j] = pack2(dt * m0, dt * m1);
            }
            float rc = 0.0f;
            #pragma unroll
            for (int i = 0; i < HDIM; i++) rc = fmaf(ws[i], b3[i], rc);
            const float cinit = dt * rc;
            init1 = pack2(cinit, 0.0f);
            float r0 = bsel;
            #pragma unroll
            for (int i = 0; i < HDIM; i++) r0 = fmaf(ws[i], h0[i], r0);
            state = r0 - cinit;
            outp = out + idx * T;
        }
    }

    // ---------------- main loop: 2 barriers per step ----------------
    for (int c = 0; c < n_chunks; c++) {
        cp_wait1();
        __syncthreads();                       // chunk data + prologue smem visible
        const int nst = min(CHUNK, T - c * CHUNK);
        const float* ub = ubuf[c & 1];
        const int tbase = c * CHUNK;

        if (is_s) {                            // du for first step of chunk
            const float* up = ub;
            float d0 = w1u[0] * up[0], d1 = w1u[1] * up[1];
            d0 = fmaf(w1u[2], up[2], d0); d1 = fmaf(w1u[3], up[3], d1);
            d0 = fmaf(w1u[4], up[4], d0); d1 = fmaf(w1u[5], up[5], d1);
            d0 = fmaf(w1u[6], up[6], d0);
            du = d0 + d1;
        }

        for (int k = 0; k < nst; k++) {
            // ---- P1: linear recurrence off z2(t-1); packed dot ----
            if (is_s) {
                float delta;
                PACKDOT64(delta, Ap, z2s, init1);
                const float y  = delta - comp;           // Kahan (R11-identical)
                const float t2 = state + y;
                comp = (t2 - state) - y;
                state = t2;
                z1s[tid] = ftanh(t2 + du);
                if (k + 1 < nst) {                       // next du off the chain
                    const float* up = ub + (k + 1) * UDIM;
                    float d0 = w1u[0] * up[0], d1 = w1u[1] * up[1];
                    d0 = fmaf(w1u[2], up[2], d0); d1 = fmaf(w1u[3], up[3], d1);
                    d0 = fmaf(w1u[4], up[4], d0); d1 = fmaf(w1u[5], up[5], d1);
                    d0 = fmaf(w1u[6], up[6], d0);
                    du = d0 + d1;
                }
            } else if (is_ro) {
                float delta;
                PACKDOT64(delta, Ap, z2s, init1);
                const float y  = delta - comp;
                const float t2 = state + y;
                comp = (t2 - state) - y;
                state = t2;
                outp[tbase + k] = state;                 // r(t) = wsel@h(t)+b
            }
            __syncthreads();                             // bar1: z1s ready, z2s reads done

            // ---- P2: z2(t) = tanh(W2 @ z1(t) + b2); packed dot ----
            if (is_s) {
                float pre;
                PACKDOT64(pre, Bp, z1s, init2);
                const float z2 = ftanh(pre);
                z2s[tid] = z2;
                accz2 += (double)z2;                     // exact hT reconstruction
            }
            __syncthreads();                             // bar2: z2s ready, z1s reads done
        }
        copy_chunk(c + 2);
        cp_commit();
    }

    // ---------------- finalize hT = h0 + dt*(W3 @ sum(z2) + T*b3) in fp64 ----------------
    __syncthreads();
    if (is_s) sumz2[tid] = accz2;
    __syncthreads();
    if (tid < HDIM) {
        double acc = (double)T * (double)b3[tid];
        #pragma unroll 8
        for (int j = 0; j < HID; j++)
            acc += (double)W3[tid * HID + j] * sumz2[j];
        out[3 * T + tid] = (float)((double)h0[tid] + (double)dt * acc);
    }
}

extern "C" void kernel_launch(void* const* d_in, const int* in_sizes, int n_in,
                              void* d_out, int out_size)
{
    const int T = in_sizes[0] / UDIM;
    node_scan_kernel<<<1, NTHREADS>>>(
        (const float*)d_in[0],                          // U
        (const float*)d_in[1], (const float*)d_in[2],   // W1, b1
        (const float*)d_in[3], (const float*)d_in[4],   // W2, b2
        (const float*)d_in[5], (const float*)d_in[6],   // W3, b3
        (const float*)d_in[7], (const float*)d_in[8],   // wd, bd
        (const float*)d_in[9], (const float*)d_in[10],  // wt, bt
        (const float*)d_in[11], (const float*)d_in[12], // wc, bc
        (const float*)d_in[13],                         // h0
        (float*)d_out, T);
}